// round 17
// baseline (speedup 1.0000x reference)
#include <cuda_runtime.h>
#include <cuda_fp16.h>
#include <cstdint>

#define N0_   292864
#define N1_   11264
#define N2_   1024
#define F0_   25
#define F1_   10
#define D_IN_ 256
#define HID_  256
#define NCLS_ 47
#define KCAT_ 512

#define CH_ROWS 16                 // rows per gather chunk
#define CH_TOT  (N1_ / CH_ROWS)    // 704 chunks
#define TILE_M  64
#define MT_TOT  (N1_ / TILE_M)     // 176 M-tiles
#define T_TOT   (MT_TOT * 2)       // 352 gemm tiles (x2 N-halves)
#define GRID_F  296                // <= 148 SMs x occ2

// ---------------- scratch (device globals; no allocation allowed) ----------
__device__ __half g_Af[N1_ * KCAT_];    // A fp16 (compacted rows)
__device__ __half g_Bf[KCAT_ * HID_];   // B fp16, [k][n]
__device__ float g_H[N1_ * HID_];       // relu(layer0), compacted rows
__device__ float g_B1T[NCLS_ * KCAT_];  // layer-1 weights, [c][k]
__device__ int   g_remap[N1_];
__device__ int   g_list[N1_];
__device__ int   g_cnt[1];
__device__ int   g_ctrA;                // gather chunk claim counter
__device__ int   g_ctrT;                // gemm tile claim counter
__device__ int   g_tile_done[MT_TOT];   // 4 chunks per M-tile

// ================= helpers =================================================
__device__ __forceinline__ uint32_t smem_u32(const void* p) {
    uint32_t a;
    asm("{ .reg .u64 t; cvta.to.shared.u64 t, %1; cvt.u32.u64 %0, t; }"
        : "=r"(a) : "l"(p));
    return a;
}
__device__ __forceinline__ void cp_async16(uint32_t dst, const void* src) {
    asm volatile("cp.async.cg.shared.global [%0], [%1], 16;"
                 :: "r"(dst), "l"(src) : "memory");
}
#define LDMX4(r, a)                                                            \
    asm volatile("ldmatrix.sync.aligned.m8n8.x4.shared.b16 {%0,%1,%2,%3}, [%4];" \
        : "=r"((r)[0]), "=r"((r)[1]), "=r"((r)[2]), "=r"((r)[3]) : "r"(a))
#define LDMX4T(r, a)                                                           \
    asm volatile("ldmatrix.sync.aligned.m8n8.x4.trans.shared.b16 {%0,%1,%2,%3}, [%4];" \
        : "=r"((r)[0]), "=r"((r)[1]), "=r"((r)[2]), "=r"((r)[3]) : "r"(a))

__device__ __forceinline__ void mma16816(float* c, const uint32_t* a,
                                         uint32_t b0, uint32_t b1) {
    asm volatile(
        "mma.sync.aligned.m16n8k16.row.col.f32.f16.f16.f32 "
        "{%0,%1,%2,%3}, {%4,%5,%6,%7}, {%8,%9}, {%0,%1,%2,%3};"
        : "+f"(c[0]), "+f"(c[1]), "+f"(c[2]), "+f"(c[3])
        : "r"(a[0]), "r"(a[1]), "r"(a[2]), "r"(a[3]), "r"(b0), "r"(b1));
}

// ================= prep: weights + remap + pipeline-state reset ============
__global__ void prep_init_kernel(const float* __restrict__ Ws0,
                                 const float* __restrict__ Wn0,
                                 const float* __restrict__ Ws1,
                                 const float* __restrict__ Wn1) {
    int idx = blockIdx.x * blockDim.x + threadIdx.x;
    if (idx < KCAT_ * HID_) {
        int k = idx / HID_, n = idx % HID_;
        float w = (k < D_IN_) ? Ws0[k * HID_ + n] : Wn0[(k - D_IN_) * HID_ + n];
        g_Bf[idx] = __float2half(w);
    }
    if (idx < NCLS_ * KCAT_) {
        int c = idx / KCAT_, k = idx % KCAT_;
        g_B1T[idx] = (k < HID_) ? Ws1[k * NCLS_ + c] : Wn1[(k - HID_) * NCLS_ + c];
    }
    if (idx < N1_) {
        g_remap[idx] = (idx < N2_) ? idx : -1;
        if (idx < N2_) g_list[idx] = idx;
    }
    if (idx < MT_TOT) g_tile_done[idx] = 0;
    if (idx == 0) { g_cnt[0] = 0; g_ctrA = 0; g_ctrT = 0; }
}

__global__ void mark_kernel(const int* __restrict__ nbr1) {
    int t = blockIdx.x * blockDim.x + threadIdx.x;
    if (t >= N2_ * F1_) return;
    int j = nbr1[t];
    if (j >= N2_) {
        if (atomicCAS(&g_remap[j], -1, -2) == -1) {
            int p = N2_ + atomicAdd(&g_cnt[0], 1);
            g_list[p] = j;
            g_remap[j] = p;
        }
    }
}

// ================= gather chunk: 16 rows -> fp16 g_Af ======================
__device__ __forceinline__ void gather_chunk16(
    int c, int ncount,
    const int* __restrict__ gids0, const int* __restrict__ nbr0,
    const float* __restrict__ emb,
    int (&sg)[CH_ROWS][26], int tid) {
    int r0 = c * CH_ROWS;
    // stage all 16x26 embedding row ids
    for (int e = tid; e < CH_ROWS * 26; e += 256) {
        int r = e / 26, j = e - r * 26;
        int b = r0 + r;
        int id = 0;
        if (b < ncount) {
            int i = g_list[b];
            id = gids0[(j == 0) ? i : nbr0[i * F0_ + (j - 1)]];
        }
        sg[r][j] = id;
    }
    __syncthreads();

    int q  = tid >> 6;      // row quad 0..3
    int lt = tid & 63;
    int ft = lt * 4;
    const float s = 1.0f / F0_;
#pragma unroll
    for (int jr = 0; jr < 4; jr++) {
        int r = q * 4 + jr;
        int b = r0 + r;
        if (b < ncount) {
            float4 xd = *(const float4*)&emb[(size_t)sg[r][0] * D_IN_ + ft];
            float4 acc = make_float4(0.f, 0.f, 0.f, 0.f);
#pragma unroll 5
            for (int j = 1; j < 26; j++) {
                float4 v = *(const float4*)&emb[(size_t)sg[r][j] * D_IN_ + ft];
                acc.x += v.x; acc.y += v.y; acc.z += v.z; acc.w += v.w;
            }
            __half2 d01 = __floats2half2_rn(xd.x, xd.y);
            __half2 d23 = __floats2half2_rn(xd.z, xd.w);
            __half2 a01 = __floats2half2_rn(acc.x * s, acc.y * s);
            __half2 a23 = __floats2half2_rn(acc.z * s, acc.w * s);
            size_t base = (size_t)b * KCAT_;
            *(__half2*)&g_Af[base + ft]             = d01;
            *(__half2*)&g_Af[base + ft + 2]         = d23;
            *(__half2*)&g_Af[base + D_IN_ + ft]     = a01;
            *(__half2*)&g_Af[base + D_IN_ + ft + 2] = a23;
        }
    }
    __threadfence();
    __syncthreads();
    if (tid == 0) atomicAdd(&g_tile_done[c >> 2], 1);
}

// ================= gemm tile: 64x128, 4-stage cp.async fp16 mma ============
#define SM_ASZ   8192
#define SM_STAGE 24576
#define SM_TOTAL (4 * SM_STAGE)

__device__ __forceinline__ void load_chunk(uint32_t sb, int buf,
                                           int bm, int bn, int kc, int tid) {
    uint32_t base = sb + buf * SM_STAGE;
#pragma unroll
    for (int i = 0; i < 2; i++) {
        int idx = tid + i * 256;
        int row = idx >> 3, c16 = idx & 7;
        size_t so = (size_t)(bm + row) * KCAT_ + kc * 64 + c16 * 8;
        uint32_t doff = row * 128 + ((c16 ^ (row & 7)) * 16);
        cp_async16(base + doff, g_Af + so);
    }
#pragma unroll
    for (int i = 0; i < 4; i++) {
        int idx = tid + i * 256;
        int k = idx >> 4, c = idx & 15;
        size_t so = (size_t)(kc * 64 + k) * HID_ + bn + c * 8;
        uint32_t doff = k * 256 + (c >> 3) * 128 + (((c & 7) ^ (k & 7)) * 16);
        cp_async16(base + SM_ASZ + doff, g_Bf + so);
    }
    asm volatile("cp.async.commit_group;" ::: "memory");
}

__device__ __forceinline__ void compute_chunk(uint32_t sb, int buf, int wm,
                                              int wn, int lane,
                                              float acc[2][4][4]) {
    uint32_t As = sb + buf * SM_STAGE;
    uint32_t Bs = As + SM_ASZ;
#pragma unroll
    for (int step = 0; step < 4; step++) {
        uint32_t a[2][4], b[2][4];
#pragma unroll
        for (int mi = 0; mi < 2; mi++) {
            int row = wm + mi * 16 + (lane & 15);
            int c16 = 2 * step + (lane >> 4);
            LDMX4(a[mi], As + row * 128 + ((c16 ^ (row & 7)) * 16));
        }
#pragma unroll
        for (int nb = 0; nb < 2; nb++) {
            int k  = step * 16 + (lane & 15);
            int cg = ((wn + nb * 16) >> 3) + (lane >> 4);
            LDMX4T(b[nb], Bs + k * 256 + (cg >> 3) * 128
                         + (((cg & 7) ^ (k & 7)) * 16));
        }
#pragma unroll
        for (int mi = 0; mi < 2; mi++)
#pragma unroll
            for (int ni = 0; ni < 4; ni++)
                mma16816(acc[mi][ni], a[mi],
                         b[ni >> 1][(ni & 1) * 2],
                         b[ni >> 1][(ni & 1) * 2 + 1]);
    }
}

__device__ __forceinline__ void gemm_tile(uint32_t sb, int bm, int bn,
                                          const float* __restrict__ b0, int tid) {
    const int lane = tid & 31;
    const int warp = tid >> 5;
    const int wm = (warp & 1) * 32;
    const int wn = (warp >> 1) * 32;

    float acc[2][4][4];
#pragma unroll
    for (int i = 0; i < 2; i++)
#pragma unroll
        for (int j = 0; j < 4; j++)
#pragma unroll
            for (int q = 0; q < 4; q++) acc[i][j][q] = 0.f;

    const int NCH = KCAT_ / 64;  // 8
    load_chunk(sb, 0, bm, bn, 0, tid);
    load_chunk(sb, 1, bm, bn, 1, tid);
    load_chunk(sb, 2, bm, bn, 2, tid);

#pragma unroll 1
    for (int cc = 0; cc < NCH; cc++) {
        asm volatile("cp.async.wait_group 2;" ::: "memory");
        __syncthreads();
        int nc = cc + 3;
        if (nc < NCH) load_chunk(sb, nc & 3, bm, bn, nc, tid);
        else asm volatile("cp.async.commit_group;" ::: "memory");
        compute_chunk(sb, cc & 3, wm, wn, lane, acc);
    }

#pragma unroll
    for (int mi = 0; mi < 2; mi++) {
#pragma unroll
        for (int ni = 0; ni < 4; ni++) {
            int col = bn + wn + ni * 8 + (lane & 3) * 2;
            float bx = __ldg(&b0[col]);
            float by = __ldg(&b0[col + 1]);
            int r0 = bm + wm + mi * 16 + (lane >> 2);
            float2 v0, v1;
            v0.x = fmaxf(acc[mi][ni][0] + bx, 0.f);
            v0.y = fmaxf(acc[mi][ni][1] + by, 0.f);
            v1.x = fmaxf(acc[mi][ni][2] + bx, 0.f);
            v1.y = fmaxf(acc[mi][ni][3] + by, 0.f);
            *(float2*)&g_H[(size_t)r0 * HID_ + col]       = v0;
            *(float2*)&g_H[(size_t)(r0 + 8) * HID_ + col] = v1;
        }
    }
}

// ================= fused pipeline: work-stealing gather + gemm =============
__global__ __launch_bounds__(256, 2) void fused_main(
    const int* __restrict__ gids0,
    const int* __restrict__ nbr0,
    const float* __restrict__ emb,
    const float* __restrict__ b0) {
    extern __shared__ char smem[];
    __shared__ int sg[CH_ROWS][26];
    __shared__ volatile int s_comm;
    const int tid = threadIdx.x;
    const uint32_t sb = smem_u32(smem);
    const int ncount = N2_ + g_cnt[0];

#pragma unroll 1
    while (true) {
        if (tid == 0) s_comm = atomicAdd(&g_ctrT, 1);
        __syncthreads();
        int tt = s_comm;
        __syncthreads();
        if (tt >= T_TOT) break;
        int m  = tt >> 1;
        int bm = m * TILE_M;
        int bn = (tt & 1) * 128;
        if (bm >= ncount) continue;

        // wait for this tile's 4 gather chunks, helping gather meanwhile
#pragma unroll 1
        while (true) {
            if (tid == 0) {
                if (atomicAdd(&g_tile_done[m], 0) >= 4) s_comm = -1;
                else                                    s_comm = atomicAdd(&g_ctrA, 1);
            }
            __syncthreads();
            int c = s_comm;
            __syncthreads();
            if (c < 0) break;                    // tile ready
            if (c < CH_TOT) gather_chunk16(c, ncount, gids0, nbr0, emb, sg, tid);
            else            __nanosleep(200);    // gather drained, tile in flight
        }
        __threadfence();

        gemm_tile(sb, bm, bn, b0, tid);
    }
}

// ================= fused layer-1: gather + mean + GEMM (warp dot) ==========
__global__ __launch_bounds__(256) void layer1_kernel(
    const int* __restrict__ nbr1,
    const float* __restrict__ b1,
    float* __restrict__ out) {
    int i = blockIdx.x;
    int t = threadIdx.x;

    __shared__ float hcat[KCAT_];
    __shared__ int sp[F1_];

    if (t < F1_) sp[t] = g_remap[nbr1[i * F1_ + t]];
    __syncthreads();

    {
        float acc = 0.f;
#pragma unroll
        for (int j = 0; j < F1_; j++) acc += g_H[(size_t)sp[j] * HID_ + t];
        hcat[t]        = g_H[(size_t)i * HID_ + t];
        hcat[HID_ + t] = acc * (1.0f / F1_);
    }
    __syncthreads();

    int w = t >> 5, l = t & 31;
    const float4* H4 = (const float4*)hcat;
#pragma unroll 1
    for (int c = w; c < NCLS_; c += 8) {
        const float4* B4 = (const float4*)(g_B1T + (size_t)c * KCAT_);
        float s = 0.f;
#pragma unroll
        for (int q = 0; q < 4; q++) {
            float4 hv = H4[l + 32 * q];
            float4 bv = B4[l + 32 * q];
            s += hv.x * bv.x + hv.y * bv.y + hv.z * bv.z + hv.w * bv.w;
        }
#pragma unroll
        for (int off = 16; off; off >>= 1)
            s += __shfl_xor_sync(0xFFFFFFFFu, s, off);
        if (l == 0) out[i * NCLS_ + c] = s + b1[c];
    }
}

// ================= launch ===================================================
extern "C" void kernel_launch(void* const* d_in, const int* in_sizes, int n_in,
                              void* d_out, int out_size) {
    const int*   gids0 = (const int*)d_in[0];
    const int*   nbr0  = (const int*)d_in[1];
    const int*   nbr1  = (const int*)d_in[2];
    const float* emb   = (const float*)d_in[3];
    const float* Ws0   = (const float*)d_in[4];
    const float* Wn0   = (const float*)d_in[5];
    const float* b0    = (const float*)d_in[6];
    const float* Ws1   = (const float*)d_in[7];
    const float* Wn1   = (const float*)d_in[8];
    const float* b1    = (const float*)d_in[9];
    float* out = (float*)d_out;

    cudaFuncSetAttribute(fused_main,
                         cudaFuncAttributeMaxDynamicSharedMemorySize, SM_TOTAL);

    prep_init_kernel<<<(KCAT_ * HID_ + 255) / 256, 256>>>(Ws0, Wn0, Ws1, Wn1);
    mark_kernel<<<(N2_ * F1_ + 255) / 256, 256>>>(nbr1);
    fused_main<<<GRID_F, 256, SM_TOTAL>>>(gids0, nbr0, emb, b0);
    layer1_kernel<<<N2_, 256>>>(nbr1, b1, out);
}